// round 14
// baseline (speedup 1.0000x reference)
#include <cuda_runtime.h>

// CounterfactualMultiheadAttention, algebraically reduced.
// Base = converged R9/R11/R13 optimum (57.44us x3). Single-variable experiment:
// fill stream count 1024 -> 512 (grid (128,B), 512KB contiguous regions) to
// probe DRAM open-row pressure. All else byte-identical.
//
// attn_weights[b,h,q,k] = unmasked[b,k] ? 1/c_b : 0   (c_b = #unmasked keys)
// ctx[b,l,:]            = (mean over unmasked l' of value[b,l',:]) @ Wv.T + bv
// output[b,l,:]         = ctx_row[b] @ Wo.T + bo      (same for every l)
//
// Q, K, Wq, bq, Wk, bk are mathematically dead.
// key_padding_mask is bool in the reference -> int32 in the harness.
//
// Schedule: self-sufficient attn_fill forks at t=0 and IS the critical path
// (268MB write stream at ~5.6 TB/s); the chain hides underneath.
// Policies (isolated): fill stores __stcs (beats wt/wb); chain loads default.

#define B 4
#define L 1024
#define D 1024
#define H 16
#define ROWS_PER_BLK 32   // colsum row-slice size
#define SPLITS 8          // gemv K-splits
#define KS (D / SPLITS)   // 128

// Scratch (no allocations allowed; device globals are the sanctioned path).
__device__ float g_vsum[B][D];     // column sums of value over unmasked rows
__device__ float g_vbar[B][D];     // vmean @ Wv.T + bv
__device__ float g_outrow[B][D];   // vbar  @ Wo.T + bo
__device__ float g_invc[B];        // 1 / c_b

// ---------------------------------------------------------------------------
// Kernel 1: per-batch unmasked count (for gemv) + accumulator zeroing.
__global__ void count_kernel(const int* __restrict__ mask) {
    int b = blockIdx.x;
    int t = threadIdx.x;

    g_vsum[b][t]   = 0.0f;         // replay-safe re-init
    g_vbar[b][t]   = 0.0f;
    g_outrow[b][t] = 0.0f;

    __shared__ int s_cnt;
    if (t == 0) s_cnt = 0;
    __syncthreads();

    int m = mask[b * L + t];
    int local = m ? 0 : 1;
    #pragma unroll
    for (int o = 16; o; o >>= 1) local += __shfl_down_sync(0xFFFFFFFFu, local, o);
    if ((t & 31) == 0) atomicAdd(&s_cnt, local);
    __syncthreads();

    if (t == 0) {
        int c = s_cnt;
        g_invc[b] = 1.0f / (float)(c > 0 ? c : 1);
    }
}

// ---------------------------------------------------------------------------
// Kernel 2: masked column partial sums of value, parallel over row slices.
// grid = (D/256, B, L/ROWS_PER_BLK) = 512 blocks, 256 threads.
__global__ void colsum_kernel(const float* __restrict__ value,
                              const int* __restrict__ mask) {
    int b  = blockIdx.y;
    int j  = blockIdx.x * 256 + threadIdx.x;
    int l0 = blockIdx.z * ROWS_PER_BLK;

    __shared__ int s_mask[ROWS_PER_BLK];
    if (threadIdx.x < ROWS_PER_BLK)
        s_mask[threadIdx.x] = mask[b * L + l0 + threadIdx.x];
    __syncthreads();

    const float* base = value + (size_t)b * L * D + (size_t)l0 * D + j;
    float acc = 0.0f;
    #pragma unroll 8
    for (int l = 0; l < ROWS_PER_BLK; l++) {
        float v = base[(size_t)l * D];
        acc += s_mask[l] ? 0.0f : v;
    }
    atomicAdd(&g_vsum[b][j], acc);
}

// ---------------------------------------------------------------------------
// Kernel 3: split-K GEMV, warp-per-output-row, all 4 batches per warp.
// grid = (D/8, SPLITS), 256 threads. Partial sums atomicAdd into destination.
__global__ void gemv_kernel(const float* __restrict__ W,
                            const float* __restrict__ bias, int mode) {
    int s  = blockIdx.y;
    int k0 = s * KS;

    __shared__ float s_in[B][KS];
    int tid = threadIdx.x;
    for (int i = tid; i < B * KS; i += 256) {
        int b = i / KS, j = i % KS;
        s_in[b][j] = (mode == 0) ? g_vsum[b][k0 + j] * g_invc[b]
                                 : g_vbar[b][k0 + j];
    }
    __syncthreads();

    int warp = tid >> 5, lane = tid & 31;
    int j = blockIdx.x * 8 + warp;
    const float4* wrow = reinterpret_cast<const float4*>(W + (size_t)j * D + k0);
    const float4* x0 = reinterpret_cast<const float4*>(s_in[0]);
    const float4* x1 = reinterpret_cast<const float4*>(s_in[1]);
    const float4* x2 = reinterpret_cast<const float4*>(s_in[2]);
    const float4* x3 = reinterpret_cast<const float4*>(s_in[3]);

    float a0 = 0.f, a1 = 0.f, a2 = 0.f, a3 = 0.f;
    #pragma unroll
    for (int i = lane; i < KS / 4; i += 32) {
        float4 w = wrow[i];
        float4 v;
        v = x0[i]; a0 += w.x*v.x + w.y*v.y + w.z*v.z + w.w*v.w;
        v = x1[i]; a1 += w.x*v.x + w.y*v.y + w.z*v.z + w.w*v.w;
        v = x2[i]; a2 += w.x*v.x + w.y*v.y + w.z*v.z + w.w*v.w;
        v = x3[i]; a3 += w.x*v.x + w.y*v.y + w.z*v.z + w.w*v.w;
    }
    #pragma unroll
    for (int o = 16; o; o >>= 1) {
        a0 += __shfl_down_sync(0xFFFFFFFFu, a0, o);
        a1 += __shfl_down_sync(0xFFFFFFFFu, a1, o);
        a2 += __shfl_down_sync(0xFFFFFFFFu, a2, o);
        a3 += __shfl_down_sync(0xFFFFFFFFu, a3, o);
    }
    if (lane == 0) {
        float bb = (s == 0) ? bias[j] : 0.0f;
        float* dst0 = (mode == 0) ? &g_vbar[0][j] : &g_outrow[0][j];
        float* dst1 = (mode == 0) ? &g_vbar[1][j] : &g_outrow[1][j];
        float* dst2 = (mode == 0) ? &g_vbar[2][j] : &g_outrow[2][j];
        float* dst3 = (mode == 0) ? &g_vbar[3][j] : &g_outrow[3][j];
        atomicAdd(dst0, a0 + bb);
        atomicAdd(dst1, a1 + bb);
        atomicAdd(dst2, a2 + bb);
        atomicAdd(dst3, a3 + bb);
    }
}

// ---------------------------------------------------------------------------
// Kernel 4: broadcast output rows, contiguous regions. grid = (64, B).
// base is a multiple of 256 => the source index is just tid, loop-invariant.
__global__ void bcast_out_kernel(float4* __restrict__ out) {
    int b   = blockIdx.y;
    int tid = threadIdx.x;
    float4 v = reinterpret_cast<const float4*>(g_outrow[b])[tid];
    float4* dst = out + (size_t)b * (L * D / 4) + (size_t)blockIdx.x * 4096;
    #pragma unroll
    for (int it = 0; it < 16; it++)
        __stcs(dst + it * 256 + tid, v);
}

// ---------------------------------------------------------------------------
// Kernel 5: fill attn_weights[b,h,q,k], SELF-SUFFICIENT, contiguous regions.
// THIS ROUND: grid = (128, B), 256 threads — 512 concurrent write streams
// (half of before), each walking a CONTIGUOUS 512KB region of 128 iterations.
// base/stride are multiples of 256 => k4 == tid always. __stcs stores.
__global__ void attn_fill_kernel(float4* __restrict__ aw,
                                 const int* __restrict__ mask) {
    int b   = blockIdx.y;
    int tid = threadIdx.x;

    int4 m = __ldg(reinterpret_cast<const int4*>(mask + b * L) + tid);
    int local = (m.x == 0) + (m.y == 0) + (m.z == 0) + (m.w == 0);

    __shared__ int   s_warp[8];
    __shared__ float s_inv;
    #pragma unroll
    for (int o = 16; o; o >>= 1) local += __shfl_down_sync(0xFFFFFFFFu, local, o);
    if ((tid & 31) == 0) s_warp[tid >> 5] = local;
    __syncthreads();
    if (tid == 0) {
        int c = s_warp[0] + s_warp[1] + s_warp[2] + s_warp[3]
              + s_warp[4] + s_warp[5] + s_warp[6] + s_warp[7];
        s_inv = 1.0f / (float)(c > 0 ? c : 1);
    }
    __syncthreads();
    float inv = s_inv;

    float4 v;
    v.x = m.x ? 0.0f : inv;
    v.y = m.y ? 0.0f : inv;
    v.z = m.z ? 0.0f : inv;
    v.w = m.w ? 0.0f : inv;

    float4* dst = aw + (size_t)b * (H * L * L / 4)
                     + (size_t)blockIdx.x * 32768;
    #pragma unroll
    for (int it = 0; it < 128; it++)
        __stcs(dst + it * 256 + tid, v);
}

// ---------------------------------------------------------------------------
extern "C" void kernel_launch(void* const* d_in, const int* in_sizes, int n_in,
                              void* d_out, int out_size) {
    // Input order: query, key, value, key_padding_mask, Wq, bq, Wk, bk, Wv, bv, Wo, bo
    const float* value = (const float*)d_in[2];
    const int*   mask  = (const int*)d_in[3];
    const float* Wv    = (const float*)d_in[8];
    const float* bv    = (const float*)d_in[9];
    const float* Wo    = (const float*)d_in[10];
    const float* bo    = (const float*)d_in[11];
    float* out = (float*)d_out;

    const long long OUT_ELEMS  = (long long)B * L * D;          //  4,194,304
    const long long ATTN_ELEMS = (long long)B * H * L * L;      // 67,108,864

    cudaStream_t s0 = 0;                 // the capture/launch stream
    cudaStream_t s2;
    cudaStreamCreateWithFlags(&s2, cudaStreamNonBlocking);
    cudaEvent_t eFork, eJoin;
    cudaEventCreateWithFlags(&eFork, cudaEventDisableTiming);
    cudaEventCreateWithFlags(&eJoin, cudaEventDisableTiming);

    // Fork IMMEDIATELY: the fill has no dependencies at all.
    cudaEventRecord(eFork, s0);
    cudaStreamWaitEvent(s2, eFork, 0);

    if ((long long)out_size >= OUT_ELEMS + ATTN_ELEMS) {
        attn_fill_kernel<<<dim3(128, B), 256, 0, s2>>>(
            (float4*)(out + OUT_ELEMS), mask);
    } else if ((long long)out_size >= ATTN_ELEMS) {
        attn_fill_kernel<<<dim3(128, B), 256, 0, s2>>>((float4*)out, mask);
    }

    // Main-stream chain: count -> colsum -> gemvV -> gemvO -> bcast
    count_kernel<<<B, L, 0, s0>>>(mask);
    colsum_kernel<<<dim3(D / 256, B, L / ROWS_PER_BLK), 256, 0, s0>>>(value, mask);
    gemv_kernel<<<dim3(D / 8, SPLITS), 256, 0, s0>>>(Wv, bv, 0);
    gemv_kernel<<<dim3(D / 8, SPLITS), 256, 0, s0>>>(Wo, bo, 1);

    if ((long long)out_size >= OUT_ELEMS + ATTN_ELEMS ||
        (long long)out_size < ATTN_ELEMS) {
        bcast_out_kernel<<<dim3(64, B), 256, 0, s0>>>((float4*)out);
    }

    // Join side stream back into the main stream.
    cudaEventRecord(eJoin, s2);
    cudaStreamWaitEvent(s0, eJoin, 0);

    cudaEventDestroy(eFork);
    cudaEventDestroy(eJoin);
    cudaStreamDestroy(s2);
}

// round 15
// speedup vs baseline: 1.1109x; 1.1109x over previous
#include <cuda_runtime.h>

// CounterfactualMultiheadAttention, algebraically reduced.
// Base = converged R9/R11/R13 optimum (57.44us x3). Stream-count bracket:
// 512 streams = 61.5 (R14), 1024 = 57.44, THIS ROUND 2048 (grid (512,B),
// 128KB contiguous regions, 32 iters) to probe the other side of the peak.
//
// attn_weights[b,h,q,k] = unmasked[b,k] ? 1/c_b : 0   (c_b = #unmasked keys)
// ctx[b,l,:]            = (mean over unmasked l' of value[b,l',:]) @ Wv.T + bv
// output[b,l,:]         = ctx_row[b] @ Wo.T + bo      (same for every l)
//
// Q, K, Wq, bq, Wk, bk are mathematically dead.
// key_padding_mask is bool in the reference -> int32 in the harness.
//
// Schedule: self-sufficient attn_fill forks at t=0 and IS the critical path
// (268MB write stream); the chain hides underneath.
// Policies (isolated): fill stores __stcs (beats wt/wb); chain loads default.

#define B 4
#define L 1024
#define D 1024
#define H 16
#define ROWS_PER_BLK 32   // colsum row-slice size
#define SPLITS 8          // gemv K-splits
#define KS (D / SPLITS)   // 128

// Scratch (no allocations allowed; device globals are the sanctioned path).
__device__ float g_vsum[B][D];     // column sums of value over unmasked rows
__device__ float g_vbar[B][D];     // vmean @ Wv.T + bv
__device__ float g_outrow[B][D];   // vbar  @ Wo.T + bo
__device__ float g_invc[B];        // 1 / c_b

// ---------------------------------------------------------------------------
// Kernel 1: per-batch unmasked count (for gemv) + accumulator zeroing.
__global__ void count_kernel(const int* __restrict__ mask) {
    int b = blockIdx.x;
    int t = threadIdx.x;

    g_vsum[b][t]   = 0.0f;         // replay-safe re-init
    g_vbar[b][t]   = 0.0f;
    g_outrow[b][t] = 0.0f;

    __shared__ int s_cnt;
    if (t == 0) s_cnt = 0;
    __syncthreads();

    int m = mask[b * L + t];
    int local = m ? 0 : 1;
    #pragma unroll
    for (int o = 16; o; o >>= 1) local += __shfl_down_sync(0xFFFFFFFFu, local, o);
    if ((t & 31) == 0) atomicAdd(&s_cnt, local);
    __syncthreads();

    if (t == 0) {
        int c = s_cnt;
        g_invc[b] = 1.0f / (float)(c > 0 ? c : 1);
    }
}

// ---------------------------------------------------------------------------
// Kernel 2: masked column partial sums of value, parallel over row slices.
// grid = (D/256, B, L/ROWS_PER_BLK) = 512 blocks, 256 threads.
__global__ void colsum_kernel(const float* __restrict__ value,
                              const int* __restrict__ mask) {
    int b  = blockIdx.y;
    int j  = blockIdx.x * 256 + threadIdx.x;
    int l0 = blockIdx.z * ROWS_PER_BLK;

    __shared__ int s_mask[ROWS_PER_BLK];
    if (threadIdx.x < ROWS_PER_BLK)
        s_mask[threadIdx.x] = mask[b * L + l0 + threadIdx.x];
    __syncthreads();

    const float* base = value + (size_t)b * L * D + (size_t)l0 * D + j;
    float acc = 0.0f;
    #pragma unroll 8
    for (int l = 0; l < ROWS_PER_BLK; l++) {
        float v = base[(size_t)l * D];
        acc += s_mask[l] ? 0.0f : v;
    }
    atomicAdd(&g_vsum[b][j], acc);
}

// ---------------------------------------------------------------------------
// Kernel 3: split-K GEMV, warp-per-output-row, all 4 batches per warp.
// grid = (D/8, SPLITS), 256 threads. Partial sums atomicAdd into destination.
__global__ void gemv_kernel(const float* __restrict__ W,
                            const float* __restrict__ bias, int mode) {
    int s  = blockIdx.y;
    int k0 = s * KS;

    __shared__ float s_in[B][KS];
    int tid = threadIdx.x;
    for (int i = tid; i < B * KS; i += 256) {
        int b = i / KS, j = i % KS;
        s_in[b][j] = (mode == 0) ? g_vsum[b][k0 + j] * g_invc[b]
                                 : g_vbar[b][k0 + j];
    }
    __syncthreads();

    int warp = tid >> 5, lane = tid & 31;
    int j = blockIdx.x * 8 + warp;
    const float4* wrow = reinterpret_cast<const float4*>(W + (size_t)j * D + k0);
    const float4* x0 = reinterpret_cast<const float4*>(s_in[0]);
    const float4* x1 = reinterpret_cast<const float4*>(s_in[1]);
    const float4* x2 = reinterpret_cast<const float4*>(s_in[2]);
    const float4* x3 = reinterpret_cast<const float4*>(s_in[3]);

    float a0 = 0.f, a1 = 0.f, a2 = 0.f, a3 = 0.f;
    #pragma unroll
    for (int i = lane; i < KS / 4; i += 32) {
        float4 w = wrow[i];
        float4 v;
        v = x0[i]; a0 += w.x*v.x + w.y*v.y + w.z*v.z + w.w*v.w;
        v = x1[i]; a1 += w.x*v.x + w.y*v.y + w.z*v.z + w.w*v.w;
        v = x2[i]; a2 += w.x*v.x + w.y*v.y + w.z*v.z + w.w*v.w;
        v = x3[i]; a3 += w.x*v.x + w.y*v.y + w.z*v.z + w.w*v.w;
    }
    #pragma unroll
    for (int o = 16; o; o >>= 1) {
        a0 += __shfl_down_sync(0xFFFFFFFFu, a0, o);
        a1 += __shfl_down_sync(0xFFFFFFFFu, a1, o);
        a2 += __shfl_down_sync(0xFFFFFFFFu, a2, o);
        a3 += __shfl_down_sync(0xFFFFFFFFu, a3, o);
    }
    if (lane == 0) {
        float bb = (s == 0) ? bias[j] : 0.0f;
        float* dst0 = (mode == 0) ? &g_vbar[0][j] : &g_outrow[0][j];
        float* dst1 = (mode == 0) ? &g_vbar[1][j] : &g_outrow[1][j];
        float* dst2 = (mode == 0) ? &g_vbar[2][j] : &g_outrow[2][j];
        float* dst3 = (mode == 0) ? &g_vbar[3][j] : &g_outrow[3][j];
        atomicAdd(dst0, a0 + bb);
        atomicAdd(dst1, a1 + bb);
        atomicAdd(dst2, a2 + bb);
        atomicAdd(dst3, a3 + bb);
    }
}

// ---------------------------------------------------------------------------
// Kernel 4: broadcast output rows, contiguous regions. grid = (64, B).
// base is a multiple of 256 => the source index is just tid, loop-invariant.
__global__ void bcast_out_kernel(float4* __restrict__ out) {
    int b   = blockIdx.y;
    int tid = threadIdx.x;
    float4 v = reinterpret_cast<const float4*>(g_outrow[b])[tid];
    float4* dst = out + (size_t)b * (L * D / 4) + (size_t)blockIdx.x * 4096;
    #pragma unroll
    for (int it = 0; it < 16; it++)
        __stcs(dst + it * 256 + tid, v);
}

// ---------------------------------------------------------------------------
// Kernel 5: fill attn_weights[b,h,q,k], SELF-SUFFICIENT, contiguous regions.
// THIS ROUND: grid = (512, B), 256 threads — 2048 write streams, each walking
// a CONTIGUOUS 128KB region of 32 iterations. base/stride are multiples of
// 256 => k4 == tid always. __stcs stores.
__global__ void attn_fill_kernel(float4* __restrict__ aw,
                                 const int* __restrict__ mask) {
    int b   = blockIdx.y;
    int tid = threadIdx.x;

    int4 m = __ldg(reinterpret_cast<const int4*>(mask + b * L) + tid);
    int local = (m.x == 0) + (m.y == 0) + (m.z == 0) + (m.w == 0);

    __shared__ int   s_warp[8];
    __shared__ float s_inv;
    #pragma unroll
    for (int o = 16; o; o >>= 1) local += __shfl_down_sync(0xFFFFFFFFu, local, o);
    if ((tid & 31) == 0) s_warp[tid >> 5] = local;
    __syncthreads();
    if (tid == 0) {
        int c = s_warp[0] + s_warp[1] + s_warp[2] + s_warp[3]
              + s_warp[4] + s_warp[5] + s_warp[6] + s_warp[7];
        s_inv = 1.0f / (float)(c > 0 ? c : 1);
    }
    __syncthreads();
    float inv = s_inv;

    float4 v;
    v.x = m.x ? 0.0f : inv;
    v.y = m.y ? 0.0f : inv;
    v.z = m.z ? 0.0f : inv;
    v.w = m.w ? 0.0f : inv;

    float4* dst = aw + (size_t)b * (H * L * L / 4)
                     + (size_t)blockIdx.x * 8192;
    #pragma unroll
    for (int it = 0; it < 32; it++)
        __stcs(dst + it * 256 + tid, v);
}

// ---------------------------------------------------------------------------
extern "C" void kernel_launch(void* const* d_in, const int* in_sizes, int n_in,
                              void* d_out, int out_size) {
    // Input order: query, key, value, key_padding_mask, Wq, bq, Wk, bk, Wv, bv, Wo, bo
    const float* value = (const float*)d_in[2];
    const int*   mask  = (const int*)d_in[3];
    const float* Wv    = (const float*)d_in[8];
    const float* bv    = (const float*)d_in[9];
    const float* Wo    = (const float*)d_in[10];
    const float* bo    = (const float*)d_in[11];
    float* out = (float*)d_out;

    const long long OUT_ELEMS  = (long long)B * L * D;          //  4,194,304
    const long long ATTN_ELEMS = (long long)B * H * L * L;      // 67,108,864

    cudaStream_t s0 = 0;                 // the capture/launch stream
    cudaStream_t s2;
    cudaStreamCreateWithFlags(&s2, cudaStreamNonBlocking);
    cudaEvent_t eFork, eJoin;
    cudaEventCreateWithFlags(&eFork, cudaEventDisableTiming);
    cudaEventCreateWithFlags(&eJoin, cudaEventDisableTiming);

    // Fork IMMEDIATELY: the fill has no dependencies at all.
    cudaEventRecord(eFork, s0);
    cudaStreamWaitEvent(s2, eFork, 0);

    if ((long long)out_size >= OUT_ELEMS + ATTN_ELEMS) {
        attn_fill_kernel<<<dim3(512, B), 256, 0, s2>>>(
            (float4*)(out + OUT_ELEMS), mask);
    } else if ((long long)out_size >= ATTN_ELEMS) {
        attn_fill_kernel<<<dim3(512, B), 256, 0, s2>>>((float4*)out, mask);
    }

    // Main-stream chain: count -> colsum -> gemvV -> gemvO -> bcast
    count_kernel<<<B, L, 0, s0>>>(mask);
    colsum_kernel<<<dim3(D / 256, B, L / ROWS_PER_BLK), 256, 0, s0>>>(value, mask);
    gemv_kernel<<<dim3(D / 8, SPLITS), 256, 0, s0>>>(Wv, bv, 0);
    gemv_kernel<<<dim3(D / 8, SPLITS), 256, 0, s0>>>(Wo, bo, 1);

    if ((long long)out_size >= OUT_ELEMS + ATTN_ELEMS ||
        (long long)out_size < ATTN_ELEMS) {
        bcast_out_kernel<<<dim3(64, B), 256, 0, s0>>>((float4*)out);
    }

    // Join side stream back into the main stream.
    cudaEventRecord(eJoin, s2);
    cudaStreamWaitEvent(s0, eJoin, 0);

    cudaEventDestroy(eFork);
    cudaEventDestroy(eJoin);
    cudaStreamDestroy(s2);
}

// round 16
// speedup vs baseline: 1.1116x; 1.0006x over previous
#include <cuda_runtime.h>

// CounterfactualMultiheadAttention, algebraically reduced.
// Stream-count gradient: 512=61.5, 1024=57.44, 2048=55.39 (R15 best).
// THIS ROUND: 4096 streams (grid (1024,B), 64KB contiguous regions, 16 iters).
//
// attn_weights[b,h,q,k] = unmasked[b,k] ? 1/c_b : 0   (c_b = #unmasked keys)
// ctx[b,l,:]            = (mean over unmasked l' of value[b,l',:]) @ Wv.T + bv
// output[b,l,:]         = ctx_row[b] @ Wo.T + bo      (same for every l)
//
// Q, K, Wq, bq, Wk, bk are mathematically dead.
// key_padding_mask is bool in the reference -> int32 in the harness.
//
// Schedule: self-sufficient attn_fill forks at t=0 and IS the critical path
// (268MB write stream); the chain hides underneath.
// Policies (isolated): fill stores __stcs (beats wt/wb); chain loads default.

#define B 4
#define L 1024
#define D 1024
#define H 16
#define ROWS_PER_BLK 32   // colsum row-slice size
#define SPLITS 8          // gemv K-splits
#define KS (D / SPLITS)   // 128

// Scratch (no allocations allowed; device globals are the sanctioned path).
__device__ float g_vsum[B][D];     // column sums of value over unmasked rows
__device__ float g_vbar[B][D];     // vmean @ Wv.T + bv
__device__ float g_outrow[B][D];   // vbar  @ Wo.T + bo
__device__ float g_invc[B];        // 1 / c_b

// ---------------------------------------------------------------------------
// Kernel 1: per-batch unmasked count (for gemv) + accumulator zeroing.
__global__ void count_kernel(const int* __restrict__ mask) {
    int b = blockIdx.x;
    int t = threadIdx.x;

    g_vsum[b][t]   = 0.0f;         // replay-safe re-init
    g_vbar[b][t]   = 0.0f;
    g_outrow[b][t] = 0.0f;

    __shared__ int s_cnt;
    if (t == 0) s_cnt = 0;
    __syncthreads();

    int m = mask[b * L + t];
    int local = m ? 0 : 1;
    #pragma unroll
    for (int o = 16; o; o >>= 1) local += __shfl_down_sync(0xFFFFFFFFu, local, o);
    if ((t & 31) == 0) atomicAdd(&s_cnt, local);
    __syncthreads();

    if (t == 0) {
        int c = s_cnt;
        g_invc[b] = 1.0f / (float)(c > 0 ? c : 1);
    }
}

// ---------------------------------------------------------------------------
// Kernel 2: masked column partial sums of value, parallel over row slices.
// grid = (D/256, B, L/ROWS_PER_BLK) = 512 blocks, 256 threads.
__global__ void colsum_kernel(const float* __restrict__ value,
                              const int* __restrict__ mask) {
    int b  = blockIdx.y;
    int j  = blockIdx.x * 256 + threadIdx.x;
    int l0 = blockIdx.z * ROWS_PER_BLK;

    __shared__ int s_mask[ROWS_PER_BLK];
    if (threadIdx.x < ROWS_PER_BLK)
        s_mask[threadIdx.x] = mask[b * L + l0 + threadIdx.x];
    __syncthreads();

    const float* base = value + (size_t)b * L * D + (size_t)l0 * D + j;
    float acc = 0.0f;
    #pragma unroll 8
    for (int l = 0; l < ROWS_PER_BLK; l++) {
        float v = base[(size_t)l * D];
        acc += s_mask[l] ? 0.0f : v;
    }
    atomicAdd(&g_vsum[b][j], acc);
}

// ---------------------------------------------------------------------------
// Kernel 3: split-K GEMV, warp-per-output-row, all 4 batches per warp.
// grid = (D/8, SPLITS), 256 threads. Partial sums atomicAdd into destination.
__global__ void gemv_kernel(const float* __restrict__ W,
                            const float* __restrict__ bias, int mode) {
    int s  = blockIdx.y;
    int k0 = s * KS;

    __shared__ float s_in[B][KS];
    int tid = threadIdx.x;
    for (int i = tid; i < B * KS; i += 256) {
        int b = i / KS, j = i % KS;
        s_in[b][j] = (mode == 0) ? g_vsum[b][k0 + j] * g_invc[b]
                                 : g_vbar[b][k0 + j];
    }
    __syncthreads();

    int warp = tid >> 5, lane = tid & 31;
    int j = blockIdx.x * 8 + warp;
    const float4* wrow = reinterpret_cast<const float4*>(W + (size_t)j * D + k0);
    const float4* x0 = reinterpret_cast<const float4*>(s_in[0]);
    const float4* x1 = reinterpret_cast<const float4*>(s_in[1]);
    const float4* x2 = reinterpret_cast<const float4*>(s_in[2]);
    const float4* x3 = reinterpret_cast<const float4*>(s_in[3]);

    float a0 = 0.f, a1 = 0.f, a2 = 0.f, a3 = 0.f;
    #pragma unroll
    for (int i = lane; i < KS / 4; i += 32) {
        float4 w = wrow[i];
        float4 v;
        v = x0[i]; a0 += w.x*v.x + w.y*v.y + w.z*v.z + w.w*v.w;
        v = x1[i]; a1 += w.x*v.x + w.y*v.y + w.z*v.z + w.w*v.w;
        v = x2[i]; a2 += w.x*v.x + w.y*v.y + w.z*v.z + w.w*v.w;
        v = x3[i]; a3 += w.x*v.x + w.y*v.y + w.z*v.z + w.w*v.w;
    }
    #pragma unroll
    for (int o = 16; o; o >>= 1) {
        a0 += __shfl_down_sync(0xFFFFFFFFu, a0, o);
        a1 += __shfl_down_sync(0xFFFFFFFFu, a1, o);
        a2 += __shfl_down_sync(0xFFFFFFFFu, a2, o);
        a3 += __shfl_down_sync(0xFFFFFFFFu, a3, o);
    }
    if (lane == 0) {
        float bb = (s == 0) ? bias[j] : 0.0f;
        float* dst0 = (mode == 0) ? &g_vbar[0][j] : &g_outrow[0][j];
        float* dst1 = (mode == 0) ? &g_vbar[1][j] : &g_outrow[1][j];
        float* dst2 = (mode == 0) ? &g_vbar[2][j] : &g_outrow[2][j];
        float* dst3 = (mode == 0) ? &g_vbar[3][j] : &g_outrow[3][j];
        atomicAdd(dst0, a0 + bb);
        atomicAdd(dst1, a1 + bb);
        atomicAdd(dst2, a2 + bb);
        atomicAdd(dst3, a3 + bb);
    }
}

// ---------------------------------------------------------------------------
// Kernel 4: broadcast output rows, contiguous regions. grid = (64, B).
// base is a multiple of 256 => the source index is just tid, loop-invariant.
__global__ void bcast_out_kernel(float4* __restrict__ out) {
    int b   = blockIdx.y;
    int tid = threadIdx.x;
    float4 v = reinterpret_cast<const float4*>(g_outrow[b])[tid];
    float4* dst = out + (size_t)b * (L * D / 4) + (size_t)blockIdx.x * 4096;
    #pragma unroll
    for (int it = 0; it < 16; it++)
        __stcs(dst + it * 256 + tid, v);
}

// ---------------------------------------------------------------------------
// Kernel 5: fill attn_weights[b,h,q,k], SELF-SUFFICIENT, contiguous regions.
// THIS ROUND: grid = (1024, B), 256 threads — 4096 write streams, each
// walking a CONTIGUOUS 64KB region of 16 iterations. base/stride are
// multiples of 256 => k4 == tid always. __stcs stores.
__global__ void attn_fill_kernel(float4* __restrict__ aw,
                                 const int* __restrict__ mask) {
    int b   = blockIdx.y;
    int tid = threadIdx.x;

    int4 m = __ldg(reinterpret_cast<const int4*>(mask + b * L) + tid);
    int local = (m.x == 0) + (m.y == 0) + (m.z == 0) + (m.w == 0);

    __shared__ int   s_warp[8];
    __shared__ float s_inv;
    #pragma unroll
    for (int o = 16; o; o >>= 1) local += __shfl_down_sync(0xFFFFFFFFu, local, o);
    if ((tid & 31) == 0) s_warp[tid >> 5] = local;
    __syncthreads();
    if (tid == 0) {
        int c = s_warp[0] + s_warp[1] + s_warp[2] + s_warp[3]
              + s_warp[4] + s_warp[5] + s_warp[6] + s_warp[7];
        s_inv = 1.0f / (float)(c > 0 ? c : 1);
    }
    __syncthreads();
    float inv = s_inv;

    float4 v;
    v.x = m.x ? 0.0f : inv;
    v.y = m.y ? 0.0f : inv;
    v.z = m.z ? 0.0f : inv;
    v.w = m.w ? 0.0f : inv;

    float4* dst = aw + (size_t)b * (H * L * L / 4)
                     + (size_t)blockIdx.x * 4096;
    #pragma unroll
    for (int it = 0; it < 16; it++)
        __stcs(dst + it * 256 + tid, v);
}

// ---------------------------------------------------------------------------
extern "C" void kernel_launch(void* const* d_in, const int* in_sizes, int n_in,
                              void* d_out, int out_size) {
    // Input order: query, key, value, key_padding_mask, Wq, bq, Wk, bk, Wv, bv, Wo, bo
    const float* value = (const float*)d_in[2];
    const int*   mask  = (const int*)d_in[3];
    const float* Wv    = (const float*)d_in[8];
    const float* bv    = (const float*)d_in[9];
    const float* Wo    = (const float*)d_in[10];
    const float* bo    = (const float*)d_in[11];
    float* out = (float*)d_out;

    const long long OUT_ELEMS  = (long long)B * L * D;          //  4,194,304
    const long long ATTN_ELEMS = (long long)B * H * L * L;      // 67,108,864

    cudaStream_t s0 = 0;                 // the capture/launch stream
    cudaStream_t s2;
    cudaStreamCreateWithFlags(&s2, cudaStreamNonBlocking);
    cudaEvent_t eFork, eJoin;
    cudaEventCreateWithFlags(&eFork, cudaEventDisableTiming);
    cudaEventCreateWithFlags(&eJoin, cudaEventDisableTiming);

    // Fork IMMEDIATELY: the fill has no dependencies at all.
    cudaEventRecord(eFork, s0);
    cudaStreamWaitEvent(s2, eFork, 0);

    if ((long long)out_size >= OUT_ELEMS + ATTN_ELEMS) {
        attn_fill_kernel<<<dim3(1024, B), 256, 0, s2>>>(
            (float4*)(out + OUT_ELEMS), mask);
    } else if ((long long)out_size >= ATTN_ELEMS) {
        attn_fill_kernel<<<dim3(1024, B), 256, 0, s2>>>((float4*)out, mask);
    }

    // Main-stream chain: count -> colsum -> gemvV -> gemvO -> bcast
    count_kernel<<<B, L, 0, s0>>>(mask);
    colsum_kernel<<<dim3(D / 256, B, L / ROWS_PER_BLK), 256, 0, s0>>>(value, mask);
    gemv_kernel<<<dim3(D / 8, SPLITS), 256, 0, s0>>>(Wv, bv, 0);
    gemv_kernel<<<dim3(D / 8, SPLITS), 256, 0, s0>>>(Wo, bo, 1);

    if ((long long)out_size >= OUT_ELEMS + ATTN_ELEMS ||
        (long long)out_size < ATTN_ELEMS) {
        bcast_out_kernel<<<dim3(64, B), 256, 0, s0>>>((float4*)out);
    }

    // Join side stream back into the main stream.
    cudaEventRecord(eJoin, s2);
    cudaStreamWaitEvent(s0, eJoin, 0);

    cudaEventDestroy(eFork);
    cudaEventDestroy(eJoin);
    cudaStreamDestroy(s2);
}